// round 1
// baseline (speedup 1.0000x reference)
#include <cuda_runtime.h>
#include <math.h>

// ---------------- problem constants ----------------
#define BATCH 128
#define EMB   384
#define NTOK  197
#define NPATCH 196
#define HEADS 6
#define HD    64
#define HID   1536
#define NE    4
#define NCLS  1000
#define MTOK  (BATCH*NTOK)      // 25216
#define MPATCH (BATCH*NPATCH)   // 25088

// ---------------- scratch (static device globals; no allocation) ----------------
__device__ float g_tok[MTOK*EMB];       // tokens + pos embed
__device__ float g_hn [MTOK*EMB];       // LN1 output
__device__ float g_kv [MTOK*768];       // [t][0:384]=k, [384:768]=v
__device__ float g_q  [BATCH*EMB];      // cls-token q
__device__ float g_att[BATCH*EMB];      // attention out (cls rows)
__device__ float g_h2 [BATCH*EMB];      // after out_proj + LN1(again)
__device__ float g_moepart[BATCH*2*EMB];
__device__ int   g_topk[BATCH*2];

__device__ __forceinline__ float warp_sum(float v) {
#pragma unroll
    for (int o = 16; o > 0; o >>= 1) v += __shfl_down_sync(0xffffffffu, v, o);
    return v;
}

__device__ __forceinline__ float gelu_exact(float v) {
    return 0.5f * v * (1.0f + erff(v * 0.70710678118654752f));
}

// ---------------- K0: cls token row init ----------------
__global__ void k0_cls(const float* __restrict__ cls, const float* __restrict__ pos) {
    int b = blockIdx.x;
    int e = threadIdx.x;                          // 384
    g_tok[(b*NTOK)*EMB + e] = cls[e] + pos[e];
}

// ---------------- K1: patch-embed GEMM  M=25088, N=384, K=768 ----------------
// A[r,k] = x[b,c,py*16+i,px*16+j] gathered on the fly; B[k,n] = conv_w[n*768+k]
__global__ void k1_patch_gemm(const float* __restrict__ x,
                              const float* __restrict__ convw,
                              const float* __restrict__ convb,
                              const float* __restrict__ pos) {
    __shared__ float As[16][64];
    __shared__ float Bs[16][64];
    int tid = threadIdx.x;                        // 256
    int tileM = blockIdx.x * 64;
    int tileN = blockIdx.y * 64;
    int tx = tid & 15, ty = tid >> 4;

    float acc[4][4] = {};

    int a_kk[4], a_rr[4], a_base[4];
#pragma unroll
    for (int u = 0; u < 4; u++) {
        int idx = tid + 256*u;
        a_kk[u] = idx & 15; a_rr[u] = idx >> 4;
        int r = tileM + a_rr[u];
        int b = r / NPATCH, p = r % NPATCH;
        int py = p / 14, px = p % 14;
        a_base[u] = b*(3*224*224) + (py*16)*224 + px*16;
    }

    for (int k0 = 0; k0 < 768; k0 += 16) {
#pragma unroll
        for (int u = 0; u < 4; u++) {
            int k = k0 + a_kk[u];
            int c = k >> 8, i = (k >> 4) & 15, j = k & 15;
            As[a_kk[u]][a_rr[u]] = x[a_base[u] + c*50176 + i*224 + j];
            int idx = tid + 256*u;
            int kk = idx & 15, nn = idx >> 4;
            Bs[kk][nn] = convw[(tileN + nn)*768 + k0 + kk];
        }
        __syncthreads();
#pragma unroll
        for (int kk = 0; kk < 16; kk++) {
            float4 av = *(const float4*)&As[kk][ty*4];
            float4 bv = *(const float4*)&Bs[kk][tx*4];
            float a[4] = {av.x, av.y, av.z, av.w};
            float bb[4] = {bv.x, bv.y, bv.z, bv.w};
#pragma unroll
            for (int i2 = 0; i2 < 4; i2++)
#pragma unroll
                for (int j2 = 0; j2 < 4; j2++)
                    acc[i2][j2] += a[i2] * bb[j2];
        }
        __syncthreads();
    }

    int n0 = tileN + tx*4;
    float4 cb = *(const float4*)&convb[n0];
#pragma unroll
    for (int i2 = 0; i2 < 4; i2++) {
        int r = tileM + ty*4 + i2;
        int b = r / NPATCH, p = r % NPATCH;
        int tok = b*NTOK + 1 + p;
        float4 pe = *(const float4*)&pos[(1+p)*EMB + n0];
        float4 o;
        o.x = acc[i2][0] + cb.x + pe.x;
        o.y = acc[i2][1] + cb.y + pe.y;
        o.z = acc[i2][2] + cb.z + pe.z;
        o.w = acc[i2][3] + cb.w + pe.w;
        *(float4*)&g_tok[tok*EMB + n0] = o;
    }
}

// ---------------- K2: LayerNorm over all tokens ----------------
__global__ void k2_ln(const float* __restrict__ g, const float* __restrict__ bt) {
    int t = blockIdx.x;
    const float* in  = g_tok + t*EMB;
    float*       out = g_hn  + t*EMB;
    int tid = threadIdx.x;                        // 128
    float x0 = in[tid], x1 = in[tid+128], x2 = in[tid+256];
    float s = x0+x1+x2, q = x0*x0 + x1*x1 + x2*x2;
    __shared__ float rs[4], rq[4];
    __shared__ float mm, rr;
    float ws = warp_sum(s), wq = warp_sum(q);
    int w = tid >> 5, l = tid & 31;
    if (l == 0) { rs[w] = ws; rq[w] = wq; }
    __syncthreads();
    if (tid == 0) {
        float S = rs[0]+rs[1]+rs[2]+rs[3];
        float Q = rq[0]+rq[1]+rq[2]+rq[3];
        float m = S * (1.0f/EMB);
        mm = m; rr = rsqrtf(Q*(1.0f/EMB) - m*m + 1e-5f);
    }
    __syncthreads();
    out[tid]     = (x0-mm)*rr*g[tid]     + bt[tid];
    out[tid+128] = (x1-mm)*rr*g[tid+128] + bt[tid+128];
    out[tid+256] = (x2-mm)*rr*g[tid+256] + bt[tid+256];
}

// ---------------- K3: K/V projection GEMM  M=25216, N=768, K=384 ----------------
__global__ void k3_kv_gemm(const float* __restrict__ W, const float* __restrict__ bias) {
    __shared__ float As[16][64];
    __shared__ float Bs[16][64];
    int tid = threadIdx.x;                        // 256
    int tileM = blockIdx.x * 64;
    int tileN = blockIdx.y * 64;
    int tx = tid & 15, ty = tid >> 4;
    float acc[4][4] = {};

    for (int k0 = 0; k0 < 384; k0 += 16) {
#pragma unroll
        for (int u = 0; u < 4; u++) {
            int idx = tid + 256*u;
            int kk = idx & 15, rr = idx >> 4;
            As[kk][rr] = g_hn[(tileM + rr)*EMB + k0 + kk];
            Bs[kk][rr] = W[(384 + tileN + rr)*EMB + k0 + kk];
        }
        __syncthreads();
#pragma unroll
        for (int kk = 0; kk < 16; kk++) {
            float4 av = *(const float4*)&As[kk][ty*4];
            float4 bv = *(const float4*)&Bs[kk][tx*4];
            float a[4] = {av.x, av.y, av.z, av.w};
            float bb[4] = {bv.x, bv.y, bv.z, bv.w};
#pragma unroll
            for (int i2 = 0; i2 < 4; i2++)
#pragma unroll
                for (int j2 = 0; j2 < 4; j2++)
                    acc[i2][j2] += a[i2] * bb[j2];
        }
        __syncthreads();
    }

    int n0 = tileN + tx*4;
    float4 bi = *(const float4*)&bias[384 + n0];
#pragma unroll
    for (int i2 = 0; i2 < 4; i2++) {
        int r = tileM + ty*4 + i2;
        float4 o;
        o.x = acc[i2][0] + bi.x;
        o.y = acc[i2][1] + bi.y;
        o.z = acc[i2][2] + bi.z;
        o.w = acc[i2][3] + bi.w;
        *(float4*)&g_kv[r*768 + n0] = o;
    }
}

// ---------------- K4: q projection for cls rows only ----------------
__global__ void k4_q(const float* __restrict__ W, const float* __restrict__ bias) {
    int b = blockIdx.x;
    __shared__ float hs[EMB];
    int tid = threadIdx.x;                        // 256
    for (int e = tid; e < EMB; e += 256) hs[e] = g_hn[(b*NTOK)*EMB + e];
    __syncthreads();
    int w = tid >> 5, l = tid & 31;
    for (int o = w; o < EMB; o += 8) {
        float p = 0.f;
        for (int e = l; e < EMB; e += 32) p += hs[e]*W[o*EMB + e];
        p = warp_sum(p);
        if (l == 0) g_q[b*EMB + o] = p + bias[o];
    }
}

// ---------------- K5: attention for cls query ----------------
__global__ void k5_attn() {
    int bh = blockIdx.x;
    int b = bh / HEADS, h = bh % HEADS;
    int tid = threadIdx.x;                        // 256
    __shared__ float qs[HD];
    __shared__ float sc[NTOK];
    __shared__ float red[256];
    if (tid < HD) qs[tid] = g_q[b*EMB + h*HD + tid];
    __syncthreads();
    int w = tid >> 5, l = tid & 31;
    const float* kvb = g_kv + b*NTOK*768;
    for (int j = w; j < NTOK; j += 8) {
        const float* kr = kvb + j*768 + h*HD;
        float p = qs[l]*kr[l] + qs[l+32]*kr[l+32];
        p = warp_sum(p);
        if (l == 0) sc[j] = p * 0.125f;
    }
    __syncthreads();
    // max
    float mx = -1e30f;
    for (int j = tid; j < NTOK; j += 256) mx = fmaxf(mx, sc[j]);
    red[tid] = mx; __syncthreads();
    for (int s = 128; s > 0; s >>= 1) { if (tid < s) red[tid] = fmaxf(red[tid], red[tid+s]); __syncthreads(); }
    mx = red[0];
    __syncthreads();
    // exp + sum
    float sm = 0.f;
    for (int j = tid; j < NTOK; j += 256) { float e = expf(sc[j]-mx); sc[j] = e; sm += e; }
    red[tid] = sm; __syncthreads();
    for (int s = 128; s > 0; s >>= 1) { if (tid < s) red[tid] += red[tid+s]; __syncthreads(); }
    float inv = 1.0f / red[0];
    __syncthreads();
    // o = sum_j att_j * v_j
    int d = tid & 63, grp = tid >> 6;
    float acc = 0.f;
    for (int j = grp; j < NTOK; j += 4)
        acc += sc[j] * kvb[j*768 + 384 + h*HD + d];
    red[tid] = acc; __syncthreads();
    if (tid < HD) {
        float o = (red[tid] + red[tid+64] + red[tid+128] + red[tid+192]) * inv;
        g_att[b*EMB + h*HD + tid] = o;
    }
}

// ---------------- K6: out_proj + second LN (ln1 params) on cls rows ----------------
__global__ void k6_proj_ln(const float* __restrict__ W, const float* __restrict__ bias,
                           const float* __restrict__ g1, const float* __restrict__ b1) {
    int b = blockIdx.x;
    int tid = threadIdx.x;                        // 256
    __shared__ float as[EMB], pr[EMB];
    __shared__ float rs[8], rq[8];
    __shared__ float mm, rr;
    for (int e = tid; e < EMB; e += 256) as[e] = g_att[b*EMB + e];
    __syncthreads();
    int w = tid >> 5, l = tid & 31;
    for (int o = w; o < EMB; o += 8) {
        float p = 0.f;
        for (int e = l; e < EMB; e += 32) p += as[e]*W[o*EMB + e];
        p = warp_sum(p);
        if (l == 0) pr[o] = p + bias[o];
    }
    __syncthreads();
    float s = 0.f, q = 0.f;
    for (int e = tid; e < EMB; e += 256) { float v = pr[e]; s += v; q += v*v; }
    s = warp_sum(s); q = warp_sum(q);
    if (l == 0) { rs[w] = s; rq[w] = q; }
    __syncthreads();
    if (tid == 0) {
        float S = 0.f, Q = 0.f;
        for (int i = 0; i < 8; i++) { S += rs[i]; Q += rq[i]; }
        float m = S*(1.0f/EMB);
        mm = m; rr = rsqrtf(Q*(1.0f/EMB) - m*m + 1e-5f);
    }
    __syncthreads();
    for (int e = tid; e < EMB; e += 256)
        g_h2[b*EMB + e] = (pr[e]-mm)*rr*g1[e] + b1[e];
}

// ---------------- K7: router + top-2 ----------------
__global__ void k7_router(const float* __restrict__ W, const float* __restrict__ bias) {
    int b = blockIdx.x;
    int tid = threadIdx.x;                        // 128
    __shared__ float hs[EMB];
    __shared__ float lg[NE];
    for (int e = tid; e < EMB; e += 128) hs[e] = g_h2[b*EMB + e];
    __syncthreads();
    int w = tid >> 5, l = tid & 31;
    if (w < NE) {
        float p = 0.f;
        for (int e = l; e < EMB; e += 32) p += hs[e]*W[w*EMB + e];
        p = warp_sum(p);
        if (l == 0) lg[w] = p + bias[w];
    }
    __syncthreads();
    if (tid == 0) {
        int i1 = 0;
        for (int i = 1; i < NE; i++) if (lg[i] > lg[i1]) i1 = i;
        int i2 = -1;
        for (int i = 0; i < NE; i++) {
            if (i == i1) continue;
            if (i2 < 0 || lg[i] > lg[i2]) i2 = i;
        }
        g_topk[b*2]   = i1;
        g_topk[b*2+1] = i2;
    }
}

// ---------------- K8: MoE expert FFN (cls rows, selected experts only) ----------------
__global__ void k8_moe(const float* __restrict__ ew1, const float* __restrict__ eb1,
                       const float* __restrict__ ew2, const float* __restrict__ eb2) {
    int b = blockIdx.x;
    int slot = blockIdx.y;                        // 0 or 1
    int tid = threadIdx.x;                        // 384
    __shared__ float hs[EMB];
    __shared__ float hid[HID];
    hs[tid] = g_h2[b*EMB + tid];
    __syncthreads();
    int e = g_topk[b*2 + slot];
    const float* W1 = ew1 + e*EMB*HID;
    float a0 = eb1[e*HID + tid];
    float a1 = eb1[e*HID + tid + 384];
    float a2 = eb1[e*HID + tid + 768];
    float a3 = eb1[e*HID + tid + 1152];
    for (int k = 0; k < EMB; k++) {
        float hv = hs[k];
        const float* row = W1 + k*HID;
        a0 += hv*row[tid];
        a1 += hv*row[tid+384];
        a2 += hv*row[tid+768];
        a3 += hv*row[tid+1152];
    }
    hid[tid]      = gelu_exact(a0);
    hid[tid+384]  = gelu_exact(a1);
    hid[tid+768]  = gelu_exact(a2);
    hid[tid+1152] = gelu_exact(a3);
    __syncthreads();
    const float* W2 = ew2 + e*HID*EMB;
    float d0 = 0.f, d1 = 0.f, d2 = 0.f, d3 = 0.f;
    for (int k = 0; k < HID; k += 4) {
        d0 += hid[k]  *W2[(k  )*EMB + tid];
        d1 += hid[k+1]*W2[(k+1)*EMB + tid];
        d2 += hid[k+2]*W2[(k+2)*EMB + tid];
        d3 += hid[k+3]*W2[(k+3)*EMB + tid];
    }
    float d = d0+d1+d2+d3 + eb2[e*EMB + tid];
    g_moepart[(b*2 + slot)*EMB + tid] = 0.5f * d;
}

// ---------------- K9: LN2 + classification head on cls tokens ----------------
__global__ void k9_head(const float* __restrict__ g2, const float* __restrict__ b2,
                        const float* __restrict__ Wh, const float* __restrict__ bh,
                        float* __restrict__ out) {
    int b = blockIdx.x;
    int tid = threadIdx.x;                        // 256
    __shared__ float hs[EMB], hl[EMB];
    __shared__ float rs[8], rq[8];
    __shared__ float mm, rr;
    for (int e = tid; e < EMB; e += 256)
        hs[e] = g_moepart[(b*2)*EMB + e] + g_moepart[(b*2+1)*EMB + e];
    __syncthreads();
    float s = 0.f, q = 0.f;
    for (int e = tid; e < EMB; e += 256) { float v = hs[e]; s += v; q += v*v; }
    s = warp_sum(s); q = warp_sum(q);
    int w = tid >> 5, l = tid & 31;
    if (l == 0) { rs[w] = s; rq[w] = q; }
    __syncthreads();
    if (tid == 0) {
        float S = 0.f, Q = 0.f;
        for (int i = 0; i < 8; i++) { S += rs[i]; Q += rq[i]; }
        float m = S*(1.0f/EMB);
        mm = m; rr = rsqrtf(Q*(1.0f/EMB) - m*m + 1e-5f);
    }
    __syncthreads();
    for (int e = tid; e < EMB; e += 256) hl[e] = (hs[e]-mm)*rr*g2[e] + b2[e];
    __syncthreads();
    for (int it = 0; it < 125; it++) {
        int c = w + 8*it;
        float p = 0.f;
        for (int e = l; e < EMB; e += 32) p += hl[e]*Wh[c*EMB + e];
        p = warp_sum(p);
        if (l == 0) out[b*NCLS + c] = p + bh[c];
    }
}

// ---------------- launcher ----------------
extern "C" void kernel_launch(void* const* d_in, const int* in_sizes, int n_in,
                              void* d_out, int out_size) {
    const float* x         = (const float*)d_in[0];
    const float* conv_w    = (const float*)d_in[1];
    const float* conv_b    = (const float*)d_in[2];
    const float* cls_token = (const float*)d_in[3];
    const float* pos_embed = (const float*)d_in[4];
    const float* ln1_g     = (const float*)d_in[5];
    const float* ln1_b     = (const float*)d_in[6];
    const float* in_proj_w = (const float*)d_in[7];
    const float* in_proj_b = (const float*)d_in[8];
    const float* out_proj_w= (const float*)d_in[9];
    const float* out_proj_b= (const float*)d_in[10];
    const float* router_w  = (const float*)d_in[11];
    const float* router_b  = (const float*)d_in[12];
    const float* ew1       = (const float*)d_in[13];
    const float* eb1       = (const float*)d_in[14];
    const float* ew2       = (const float*)d_in[15];
    const float* eb2       = (const float*)d_in[16];
    const float* ln2_g     = (const float*)d_in[17];
    const float* ln2_b     = (const float*)d_in[18];
    const float* head_w    = (const float*)d_in[19];
    const float* head_b    = (const float*)d_in[20];
    float* out = (float*)d_out;

    k0_cls<<<BATCH, EMB>>>(cls_token, pos_embed);
    k1_patch_gemm<<<dim3(MPATCH/64, EMB/64), 256>>>(x, conv_w, conv_b, pos_embed);
    k2_ln<<<MTOK, 128>>>(ln1_g, ln1_b);
    k3_kv_gemm<<<dim3(MTOK/64, 768/64), 256>>>(in_proj_w, in_proj_b);
    k4_q<<<BATCH, 256>>>(in_proj_w, in_proj_b);
    k5_attn<<<BATCH*HEADS, 256>>>();
    k6_proj_ln<<<BATCH, 256>>>(out_proj_w, out_proj_b, ln1_g, ln1_b);
    k7_router<<<BATCH, 128>>>(router_w, router_b);
    k8_moe<<<dim3(BATCH, 2), EMB>>>(ew1, eb1, ew2, eb2);
    k9_head<<<BATCH, 256>>>(ln2_g, ln2_b, head_w, head_b, out);
}

// round 2
// speedup vs baseline: 1.6480x; 1.6480x over previous
#include <cuda_runtime.h>
#include <math.h>

// ---------------- problem constants ----------------
#define BATCH 128
#define EMB   384
#define NTOK  197
#define NPATCH 196
#define HEADS 6
#define HD    64
#define HID   1536
#define NE    4
#define NCLS  1000
#define MTOK  (BATCH*NTOK)      // 25216 = 128*197
#define MPATCH (BATCH*NPATCH)   // 25088 = 128*196

// ---------------- scratch (static device globals; no allocation) ----------------
__device__ float g_tok[MTOK*EMB];       // tokens + pos embed
__device__ float g_hn [MTOK*EMB];       // LN1 output
__device__ float g_kv [MTOK*768];       // [t][0:384]=k, [384:768]=v
__device__ float g_q  [BATCH*EMB];      // cls-token q
__device__ float g_att[BATCH*EMB];      // attention out (cls rows)
__device__ float g_h2 [BATCH*EMB];      // after out_proj + LN1(again)
__device__ float g_moepart[BATCH*2*EMB];
__device__ int   g_topk[BATCH*2];

__device__ __forceinline__ float warp_sum(float v) {
#pragma unroll
    for (int o = 16; o > 0; o >>= 1) v += __shfl_down_sync(0xffffffffu, v, o);
    return v;
}

__device__ __forceinline__ float gelu_exact(float v) {
    return 0.5f * v * (1.0f + erff(v * 0.70710678118654752f));
}

// ---------------- K0: cls token row init ----------------
__global__ void k0_cls(const float* __restrict__ cls, const float* __restrict__ pos) {
    int b = blockIdx.x;
    int e = threadIdx.x;                          // 384
    g_tok[(b*NTOK)*EMB + e] = cls[e] + pos[e];
}

// ================= high-intensity SGEMM kernels: 128x128x16 tile, 8x8 micro =================
// 256 threads; tx = tid&15 (N dir), ty = tid>>4 (M dir). Each thread: acc[8][8].
// Smem: As[16][128] k-major, Bs[16][128] k-major. Per-thread global load: 2 float4 A + 2 float4 B.

// ---------------- K1: patch-embed GEMM  M=25088, N=384, K=768 ----------------
__global__ void __launch_bounds__(256) k1_patch_gemm(
        const float* __restrict__ x,
        const float* __restrict__ convw,
        const float* __restrict__ convb,
        const float* __restrict__ pos) {
    __shared__ float As[16][128];
    __shared__ float Bs[16][128];
    int tid = threadIdx.x;
    int tileM = blockIdx.x * 128;
    int tileN = blockIdx.y * 128;
    int tx = tid & 15, ty = tid >> 4;

    // A-gather geometry per loaded row (2 rows per thread, fixed across k)
    int a_row[2], a_kkf4[2], a_base[2];
    int b_row[2], b_kkf4[2];
#pragma unroll
    for (int u = 0; u < 2; u++) {
        int i = tid + 256*u;
        a_row[u] = i >> 2; a_kkf4[u] = (i & 3) * 4;
        int r = tileM + a_row[u];
        int b = r / NPATCH, p = r % NPATCH;
        int py = p / 14, px = p % 14;
        a_base[u] = b*(3*224*224) + (py*16)*224 + px*16;
        b_row[u] = i >> 2; b_kkf4[u] = (i & 3) * 4;
    }

    float4 pa[2], pb[2];
    float acc[8][8] = {};

    // prologue: load k-tile 0
#pragma unroll
    for (int u = 0; u < 2; u++) {
        int k = a_kkf4[u];                         // k0 = 0
        int c = k >> 8, ii = (k >> 4) & 15, j = k & 15;
        pa[u] = *(const float4*)&x[a_base[u] + c*50176 + ii*224 + j];
        pb[u] = *(const float4*)&convw[(tileN + b_row[u])*768 + b_kkf4[u]];
    }

    for (int kt = 0; kt < 48; kt++) {
        // commit prefetched regs to smem
#pragma unroll
        for (int u = 0; u < 2; u++) {
            As[a_kkf4[u]+0][a_row[u]] = pa[u].x;
            As[a_kkf4[u]+1][a_row[u]] = pa[u].y;
            As[a_kkf4[u]+2][a_row[u]] = pa[u].z;
            As[a_kkf4[u]+3][a_row[u]] = pa[u].w;
            Bs[b_kkf4[u]+0][b_row[u]] = pb[u].x;
            Bs[b_kkf4[u]+1][b_row[u]] = pb[u].y;
            Bs[b_kkf4[u]+2][b_row[u]] = pb[u].z;
            Bs[b_kkf4[u]+3][b_row[u]] = pb[u].w;
        }
        __syncthreads();
        // prefetch next k-tile
        if (kt < 47) {
            int k0n = (kt+1) * 16;
#pragma unroll
            for (int u = 0; u < 2; u++) {
                int k = k0n + a_kkf4[u];
                int c = k >> 8, ii = (k >> 4) & 15, j = k & 15;
                pa[u] = *(const float4*)&x[a_base[u] + c*50176 + ii*224 + j];
                pb[u] = *(const float4*)&convw[(tileN + b_row[u])*768 + k0n + b_kkf4[u]];
            }
        }
        // compute
#pragma unroll
        for (int kk = 0; kk < 16; kk++) {
            float4 a0 = *(const float4*)&As[kk][ty*8];
            float4 a1 = *(const float4*)&As[kk][ty*8+4];
            float4 b0 = *(const float4*)&Bs[kk][tx*8];
            float4 b1 = *(const float4*)&Bs[kk][tx*8+4];
            float a[8] = {a0.x,a0.y,a0.z,a0.w,a1.x,a1.y,a1.z,a1.w};
            float bb[8] = {b0.x,b0.y,b0.z,b0.w,b1.x,b1.y,b1.z,b1.w};
#pragma unroll
            for (int i2 = 0; i2 < 8; i2++)
#pragma unroll
                for (int j2 = 0; j2 < 8; j2++)
                    acc[i2][j2] += a[i2] * bb[j2];
        }
        __syncthreads();
    }

    int n0 = tileN + tx*8;
    float4 cb0 = *(const float4*)&convb[n0];
    float4 cb1 = *(const float4*)&convb[n0+4];
#pragma unroll
    for (int i2 = 0; i2 < 8; i2++) {
        int r = tileM + ty*8 + i2;
        int b = r / NPATCH, p = r % NPATCH;
        int tok = b*NTOK + 1 + p;
        float4 pe0 = *(const float4*)&pos[(1+p)*EMB + n0];
        float4 pe1 = *(const float4*)&pos[(1+p)*EMB + n0+4];
        float4 o0, o1;
        o0.x = acc[i2][0]+cb0.x+pe0.x; o0.y = acc[i2][1]+cb0.y+pe0.y;
        o0.z = acc[i2][2]+cb0.z+pe0.z; o0.w = acc[i2][3]+cb0.w+pe0.w;
        o1.x = acc[i2][4]+cb1.x+pe1.x; o1.y = acc[i2][5]+cb1.y+pe1.y;
        o1.z = acc[i2][6]+cb1.z+pe1.z; o1.w = acc[i2][7]+cb1.w+pe1.w;
        *(float4*)&g_tok[tok*EMB + n0]   = o0;
        *(float4*)&g_tok[tok*EMB + n0+4] = o1;
    }
}

// ---------------- K3: K/V projection GEMM  M=25216, N=768, K=384 ----------------
__global__ void __launch_bounds__(256) k3_kv_gemm(
        const float* __restrict__ W, const float* __restrict__ bias) {
    __shared__ float As[16][128];
    __shared__ float Bs[16][128];
    int tid = threadIdx.x;
    int tileM = blockIdx.x * 128;
    int tileN = blockIdx.y * 128;
    int tx = tid & 15, ty = tid >> 4;

    int row[2], kkf4[2];
#pragma unroll
    for (int u = 0; u < 2; u++) {
        int i = tid + 256*u;
        row[u] = i >> 2; kkf4[u] = (i & 3) * 4;
    }

    float4 pa[2], pb[2];
    float acc[8][8] = {};

#pragma unroll
    for (int u = 0; u < 2; u++) {
        pa[u] = *(const float4*)&g_hn[(tileM + row[u])*EMB + kkf4[u]];
        pb[u] = *(const float4*)&W[(384 + tileN + row[u])*EMB + kkf4[u]];
    }

    for (int kt = 0; kt < 24; kt++) {
#pragma unroll
        for (int u = 0; u < 2; u++) {
            As[kkf4[u]+0][row[u]] = pa[u].x;
            As[kkf4[u]+1][row[u]] = pa[u].y;
            As[kkf4[u]+2][row[u]] = pa[u].z;
            As[kkf4[u]+3][row[u]] = pa[u].w;
            Bs[kkf4[u]+0][row[u]] = pb[u].x;
            Bs[kkf4[u]+1][row[u]] = pb[u].y;
            Bs[kkf4[u]+2][row[u]] = pb[u].z;
            Bs[kkf4[u]+3][row[u]] = pb[u].w;
        }
        __syncthreads();
        if (kt < 23) {
            int k0n = (kt+1) * 16;
#pragma unroll
            for (int u = 0; u < 2; u++) {
                pa[u] = *(const float4*)&g_hn[(tileM + row[u])*EMB + k0n + kkf4[u]];
                pb[u] = *(const float4*)&W[(384 + tileN + row[u])*EMB + k0n + kkf4[u]];
            }
        }
#pragma unroll
        for (int kk = 0; kk < 16; kk++) {
            float4 a0 = *(const float4*)&As[kk][ty*8];
            float4 a1 = *(const float4*)&As[kk][ty*8+4];
            float4 b0 = *(const float4*)&Bs[kk][tx*8];
            float4 b1 = *(const float4*)&Bs[kk][tx*8+4];
            float a[8] = {a0.x,a0.y,a0.z,a0.w,a1.x,a1.y,a1.z,a1.w};
            float bb[8] = {b0.x,b0.y,b0.z,b0.w,b1.x,b1.y,b1.z,b1.w};
#pragma unroll
            for (int i2 = 0; i2 < 8; i2++)
#pragma unroll
                for (int j2 = 0; j2 < 8; j2++)
                    acc[i2][j2] += a[i2] * bb[j2];
        }
        __syncthreads();
    }

    int n0 = tileN + tx*8;
    float4 bi0 = *(const float4*)&bias[384 + n0];
    float4 bi1 = *(const float4*)&bias[384 + n0 + 4];
#pragma unroll
    for (int i2 = 0; i2 < 8; i2++) {
        int r = tileM + ty*8 + i2;
        float4 o0, o1;
        o0.x = acc[i2][0]+bi0.x; o0.y = acc[i2][1]+bi0.y;
        o0.z = acc[i2][2]+bi0.z; o0.w = acc[i2][3]+bi0.w;
        o1.x = acc[i2][4]+bi1.x; o1.y = acc[i2][5]+bi1.y;
        o1.z = acc[i2][6]+bi1.z; o1.w = acc[i2][7]+bi1.w;
        *(float4*)&g_kv[r*768 + n0]   = o0;
        *(float4*)&g_kv[r*768 + n0+4] = o1;
    }
}

// ---------------- K2: LayerNorm over all tokens ----------------
__global__ void k2_ln(const float* __restrict__ g, const float* __restrict__ bt) {
    int t = blockIdx.x;
    const float* in  = g_tok + t*EMB;
    float*       out = g_hn  + t*EMB;
    int tid = threadIdx.x;                        // 128
    float x0 = in[tid], x1 = in[tid+128], x2 = in[tid+256];
    float s = x0+x1+x2, q = x0*x0 + x1*x1 + x2*x2;
    __shared__ float rs[4], rq[4];
    __shared__ float mm, rr;
    float ws = warp_sum(s), wq = warp_sum(q);
    int w = tid >> 5, l = tid & 31;
    if (l == 0) { rs[w] = ws; rq[w] = wq; }
    __syncthreads();
    if (tid == 0) {
        float S = rs[0]+rs[1]+rs[2]+rs[3];
        float Q = rq[0]+rq[1]+rq[2]+rq[3];
        float m = S * (1.0f/EMB);
        mm = m; rr = rsqrtf(Q*(1.0f/EMB) - m*m + 1e-5f);
    }
    __syncthreads();
    out[tid]     = (x0-mm)*rr*g[tid]     + bt[tid];
    out[tid+128] = (x1-mm)*rr*g[tid+128] + bt[tid+128];
    out[tid+256] = (x2-mm)*rr*g[tid+256] + bt[tid+256];
}

// ---------------- K4: q projection for cls rows only ----------------
__global__ void k4_q(const float* __restrict__ W, const float* __restrict__ bias) {
    int b = blockIdx.x;
    __shared__ float hs[EMB];
    int tid = threadIdx.x;                        // 256
    for (int e = tid; e < EMB; e += 256) hs[e] = g_hn[(b*NTOK)*EMB + e];
    __syncthreads();
    int w = tid >> 5, l = tid & 31;
    for (int o = w; o < EMB; o += 8) {
        float p = 0.f;
        for (int e = l; e < EMB; e += 32) p += hs[e]*W[o*EMB + e];
        p = warp_sum(p);
        if (l == 0) g_q[b*EMB + o] = p + bias[o];
    }
}

// ---------------- K5: attention for cls query ----------------
__global__ void k5_attn() {
    int bh = blockIdx.x;
    int b = bh / HEADS, h = bh % HEADS;
    int tid = threadIdx.x;                        // 256
    __shared__ float qs[HD];
    __shared__ float sc[NTOK];
    __shared__ float red[256];
    if (tid < HD) qs[tid] = g_q[b*EMB + h*HD + tid];
    __syncthreads();
    int w = tid >> 5, l = tid & 31;
    const float* kvb = g_kv + b*NTOK*768;
    for (int j = w; j < NTOK; j += 8) {
        const float* kr = kvb + j*768 + h*HD;
        float p = qs[l]*kr[l] + qs[l+32]*kr[l+32];
        p = warp_sum(p);
        if (l == 0) sc[j] = p * 0.125f;
    }
    __syncthreads();
    float mx = -1e30f;
    for (int j = tid; j < NTOK; j += 256) mx = fmaxf(mx, sc[j]);
    red[tid] = mx; __syncthreads();
    for (int s = 128; s > 0; s >>= 1) { if (tid < s) red[tid] = fmaxf(red[tid], red[tid+s]); __syncthreads(); }
    mx = red[0];
    __syncthreads();
    float sm = 0.f;
    for (int j = tid; j < NTOK; j += 256) { float e = expf(sc[j]-mx); sc[j] = e; sm += e; }
    red[tid] = sm; __syncthreads();
    for (int s = 128; s > 0; s >>= 1) { if (tid < s) red[tid] += red[tid+s]; __syncthreads(); }
    float inv = 1.0f / red[0];
    __syncthreads();
    int d = tid & 63, grp = tid >> 6;
    float acc = 0.f;
    for (int j = grp; j < NTOK; j += 4)
        acc += sc[j] * kvb[j*768 + 384 + h*HD + d];
    red[tid] = acc; __syncthreads();
    if (tid < HD) {
        float o = (red[tid] + red[tid+64] + red[tid+128] + red[tid+192]) * inv;
        g_att[b*EMB + h*HD + tid] = o;
    }
}

// ---------------- K6: out_proj + second LN (ln1 params) on cls rows ----------------
__global__ void k6_proj_ln(const float* __restrict__ W, const float* __restrict__ bias,
                           const float* __restrict__ g1, const float* __restrict__ b1) {
    int b = blockIdx.x;
    int tid = threadIdx.x;                        // 256
    __shared__ float as[EMB], pr[EMB];
    __shared__ float rs[8], rq[8];
    __shared__ float mm, rr;
    for (int e = tid; e < EMB; e += 256) as[e] = g_att[b*EMB + e];
    __syncthreads();
    int w = tid >> 5, l = tid & 31;
    for (int o = w; o < EMB; o += 8) {
        float p = 0.f;
        for (int e = l; e < EMB; e += 32) p += as[e]*W[o*EMB + e];
        p = warp_sum(p);
        if (l == 0) pr[o] = p + bias[o];
    }
    __syncthreads();
    float s = 0.f, q = 0.f;
    for (int e = tid; e < EMB; e += 256) { float v = pr[e]; s += v; q += v*v; }
    s = warp_sum(s); q = warp_sum(q);
    if (l == 0) { rs[w] = s; rq[w] = q; }
    __syncthreads();
    if (tid == 0) {
        float S = 0.f, Q = 0.f;
        for (int i = 0; i < 8; i++) { S += rs[i]; Q += rq[i]; }
        float m = S*(1.0f/EMB);
        mm = m; rr = rsqrtf(Q*(1.0f/EMB) - m*m + 1e-5f);
    }
    __syncthreads();
    for (int e = tid; e < EMB; e += 256)
        g_h2[b*EMB + e] = (pr[e]-mm)*rr*g1[e] + b1[e];
}

// ---------------- K7: router + top-2 ----------------
__global__ void k7_router(const float* __restrict__ W, const float* __restrict__ bias) {
    int b = blockIdx.x;
    int tid = threadIdx.x;                        // 128
    __shared__ float hs[EMB];
    __shared__ float lg[NE];
    for (int e = tid; e < EMB; e += 128) hs[e] = g_h2[b*EMB + e];
    __syncthreads();
    int w = tid >> 5, l = tid & 31;
    if (w < NE) {
        float p = 0.f;
        for (int e = l; e < EMB; e += 32) p += hs[e]*W[w*EMB + e];
        p = warp_sum(p);
        if (l == 0) lg[w] = p + bias[w];
    }
    __syncthreads();
    if (tid == 0) {
        int i1 = 0;
        for (int i = 1; i < NE; i++) if (lg[i] > lg[i1]) i1 = i;
        int i2 = -1;
        for (int i = 0; i < NE; i++) {
            if (i == i1) continue;
            if (i2 < 0 || lg[i] > lg[i2]) i2 = i;
        }
        g_topk[b*2]   = i1;
        g_topk[b*2+1] = i2;
    }
}

// ---------------- K8: MoE expert FFN (cls rows, selected experts only) ----------------
__global__ void k8_moe(const float* __restrict__ ew1, const float* __restrict__ eb1,
                       const float* __restrict__ ew2, const float* __restrict__ eb2) {
    int b = blockIdx.x;
    int slot = blockIdx.y;                        // 0 or 1
    int tid = threadIdx.x;                        // 384
    __shared__ float hs[EMB];
    __shared__ float hid[HID];
    hs[tid] = g_h2[b*EMB + tid];
    __syncthreads();
    int e = g_topk[b*2 + slot];
    const float* W1 = ew1 + e*EMB*HID;
    float a0 = eb1[e*HID + tid];
    float a1 = eb1[e*HID + tid + 384];
    float a2 = eb1[e*HID + tid + 768];
    float a3 = eb1[e*HID + tid + 1152];
    for (int k = 0; k < EMB; k++) {
        float hv = hs[k];
        const float* row = W1 + k*HID;
        a0 += hv*row[tid];
        a1 += hv*row[tid+384];
        a2 += hv*row[tid+768];
        a3 += hv*row[tid+1152];
    }
    hid[tid]      = gelu_exact(a0);
    hid[tid+384]  = gelu_exact(a1);
    hid[tid+768]  = gelu_exact(a2);
    hid[tid+1152] = gelu_exact(a3);
    __syncthreads();
    const float* W2 = ew2 + e*HID*EMB;
    float d0 = 0.f, d1 = 0.f, d2 = 0.f, d3 = 0.f;
    for (int k = 0; k < HID; k += 4) {
        d0 += hid[k]  *W2[(k  )*EMB + tid];
        d1 += hid[k+1]*W2[(k+1)*EMB + tid];
        d2 += hid[k+2]*W2[(k+2)*EMB + tid];
        d3 += hid[k+3]*W2[(k+3)*EMB + tid];
    }
    float d = d0+d1+d2+d3 + eb2[e*EMB + tid];
    g_moepart[(b*2 + slot)*EMB + tid] = 0.5f * d;
}

// ---------------- K9: LN2 + classification head on cls tokens ----------------
__global__ void k9_head(const float* __restrict__ g2, const float* __restrict__ b2,
                        const float* __restrict__ Wh, const float* __restrict__ bh,
                        float* __restrict__ out) {
    int b = blockIdx.x;
    int tid = threadIdx.x;                        // 256
    __shared__ float hs[EMB], hl[EMB];
    __shared__ float rs[8], rq[8];
    __shared__ float mm, rr;
    for (int e = tid; e < EMB; e += 256)
        hs[e] = g_moepart[(b*2)*EMB + e] + g_moepart[(b*2+1)*EMB + e];
    __syncthreads();
    float s = 0.f, q = 0.f;
    for (int e = tid; e < EMB; e += 256) { float v = hs[e]; s += v; q += v*v; }
    s = warp_sum(s); q = warp_sum(q);
    int w = tid >> 5, l = tid & 31;
    if (l == 0) { rs[w] = s; rq[w] = q; }
    __syncthreads();
    if (tid == 0) {
        float S = 0.f, Q = 0.f;
        for (int i = 0; i < 8; i++) { S += rs[i]; Q += rq[i]; }
        float m = S*(1.0f/EMB);
        mm = m; rr = rsqrtf(Q*(1.0f/EMB) - m*m + 1e-5f);
    }
    __syncthreads();
    for (int e = tid; e < EMB; e += 256) hl[e] = (hs[e]-mm)*rr*g2[e] + b2[e];
    __syncthreads();
    for (int it = 0; it < 125; it++) {
        int c = w + 8*it;
        float p = 0.f;
        for (int e = l; e < EMB; e += 32) p += hl[e]*Wh[c*EMB + e];
        p = warp_sum(p);
        if (l == 0) out[b*NCLS + c] = p + bh[c];
    }
}

// ---------------- launcher ----------------
extern "C" void kernel_launch(void* const* d_in, const int* in_sizes, int n_in,
                              void* d_out, int out_size) {
    const float* x         = (const float*)d_in[0];
    const float* conv_w    = (const float*)d_in[1];
    const float* conv_b    = (const float*)d_in[2];
    const float* cls_token = (const float*)d_in[3];
    const float* pos_embed = (const float*)d_in[4];
    const float* ln1_g     = (const float*)d_in[5];
    const float* ln1_b     = (const float*)d_in[6];
    const float* in_proj_w = (const float*)d_in[7];
    const float* in_proj_b = (const float*)d_in[8];
    const float* out_proj_w= (const float*)d_in[9];
    const float* out_proj_b= (const float*)d_in[10];
    const float* router_w  = (const float*)d_in[11];
    const float* router_b  = (const float*)d_in[12];
    const float* ew1       = (const float*)d_in[13];
    const float* eb1       = (const float*)d_in[14];
    const float* ew2       = (const float*)d_in[15];
    const float* eb2       = (const float*)d_in[16];
    const float* ln2_g     = (const float*)d_in[17];
    const float* ln2_b     = (const float*)d_in[18];
    const float* head_w    = (const float*)d_in[19];
    const float* head_b    = (const float*)d_in[20];
    float* out = (float*)d_out;

    k0_cls<<<BATCH, EMB>>>(cls_token, pos_embed);
    k1_patch_gemm<<<dim3(MPATCH/128, EMB/128), 256>>>(x, conv_w, conv_b, pos_embed);
    k2_ln<<<MTOK, 128>>>(ln1_g, ln1_b);
    k3_kv_gemm<<<dim3(MTOK/128, 768/128), 256>>>(in_proj_w, in_proj_b);
    k4_q<<<BATCH, 256>>>(in_proj_w, in_proj_b);
    k5_attn<<<BATCH*HEADS, 256>>>();
    k6_proj_ln<<<BATCH, 256>>>(out_proj_w, out_proj_b, ln1_g, ln1_b);
    k7_router<<<BATCH, 128>>>(router_w, router_b);
    k8_moe<<<dim3(BATCH, 2), EMB>>>(ew1, eb1, ew2, eb2);
    k9_head<<<BATCH, 256>>>(ln2_g, ln2_b, head_w, head_b, out);
}

// round 4
// speedup vs baseline: 2.3356x; 1.4172x over previous
#include <cuda_runtime.h>
#include <cuda_bf16.h>
#include <math.h>
#include <stdint.h>

// ---------------- problem constants ----------------
#define BATCH 128
#define EMB   384
#define NTOK  197
#define NPATCH 196
#define HEADS 6
#define HD    64
#define HID   1536
#define NE    4
#define NCLS  1000
#define MTOK  (BATCH*NTOK)      // 25216 = 197*128
#define MPATCH (BATCH*NPATCH)   // 25088 = 196*128
#define SSTR  40                // smem row stride in bf16 halves (conflict-free)

// ---------------- scratch (static device globals; no allocation) ----------------
__device__ float g_tok[MTOK*EMB];
__device__ float g_hn [MTOK*EMB];
__device__ float g_kv [MTOK*768];
__device__ float g_q  [BATCH*EMB];
__device__ float g_att[BATCH*EMB];
__device__ float g_h2 [BATCH*EMB];
__device__ float g_moepart[BATCH*2*EMB];
__device__ int   g_topk[BATCH*2];
__device__ int   g_ecnt[NE];
__device__ int   g_elist[NE*256];

__device__ __forceinline__ float warp_sum(float v) {
#pragma unroll
    for (int o = 16; o > 0; o >>= 1) v += __shfl_down_sync(0xffffffffu, v, o);
    return v;
}
__device__ __forceinline__ float gelu_exact(float v) {
    return 0.5f * v * (1.0f + erff(v * 0.70710678118654752f));
}

// mma.sync m16n8k16 bf16 -> f32 (legacy HMMA path; works on plain sm_103 target)
__device__ __forceinline__ void mma_bf16(float* c, const uint32_t* a, const uint32_t* b) {
    asm volatile(
        "mma.sync.aligned.m16n8k16.row.col.f32.bf16.bf16.f32 "
        "{%0,%1,%2,%3}, {%4,%5,%6,%7}, {%8,%9}, {%0,%1,%2,%3};"
        : "+f"(c[0]), "+f"(c[1]), "+f"(c[2]), "+f"(c[3])
        : "r"(a[0]), "r"(a[1]), "r"(a[2]), "r"(a[3]), "r"(b[0]), "r"(b[1]));
}

// split fp32x4 -> bf16 hi/lo, store 4 halves (8B) to smem at [row][c4]
__device__ __forceinline__ void store_split4(__nv_bfloat16* hiB, __nv_bfloat16* loB,
                                             int row, int c4, float4 v) {
    __nv_bfloat16 h0 = __float2bfloat16_rn(v.x);
    __nv_bfloat16 h1 = __float2bfloat16_rn(v.y);
    __nv_bfloat16 h2 = __float2bfloat16_rn(v.z);
    __nv_bfloat16 h3 = __float2bfloat16_rn(v.w);
    __nv_bfloat16 l0 = __float2bfloat16_rn(v.x - __bfloat162float(h0));
    __nv_bfloat16 l1 = __float2bfloat16_rn(v.y - __bfloat162float(h1));
    __nv_bfloat16 l2 = __float2bfloat16_rn(v.z - __bfloat162float(h2));
    __nv_bfloat16 l3 = __float2bfloat16_rn(v.w - __bfloat162float(h3));
    uint2 hp, lp;
    hp.x = ((uint32_t)__bfloat16_as_ushort(h1) << 16) | __bfloat16_as_ushort(h0);
    hp.y = ((uint32_t)__bfloat16_as_ushort(h3) << 16) | __bfloat16_as_ushort(h2);
    lp.x = ((uint32_t)__bfloat16_as_ushort(l1) << 16) | __bfloat16_as_ushort(l0);
    lp.y = ((uint32_t)__bfloat16_as_ushort(l3) << 16) | __bfloat16_as_ushort(l2);
    *(uint2*)&hiB[row*SSTR + c4] = hp;
    *(uint2*)&loB[row*SSTR + c4] = lp;
}

// load A frag (m16k16) hi set from smem: base row r0, k-col kk
__device__ __forceinline__ void load_afrag(uint32_t* a, const __nv_bfloat16* S, int r0, int kk) {
    a[0] = *(const uint32_t*)&S[(r0    )*SSTR + kk    ];
    a[1] = *(const uint32_t*)&S[(r0 + 8)*SSTR + kk    ];
    a[2] = *(const uint32_t*)&S[(r0    )*SSTR + kk + 8];
    a[3] = *(const uint32_t*)&S[(r0 + 8)*SSTR + kk + 8];
}
__device__ __forceinline__ void load_bfrag(uint32_t* b, const __nv_bfloat16* S, int n0, int kk) {
    b[0] = *(const uint32_t*)&S[n0*SSTR + kk    ];
    b[1] = *(const uint32_t*)&S[n0*SSTR + kk + 8];
}

// ---------------- K0: cls token row init ----------------
__global__ void k0_cls(const float* __restrict__ cls, const float* __restrict__ pos) {
    int b = blockIdx.x;
    int e = threadIdx.x;
    g_tok[(b*NTOK)*EMB + e] = cls[e] + pos[e];
}

// ================= HMMA GEMM: block 128x128, 8 warps (64x32 each), K-chunk 32, split-bf16 ====

// ---------------- K1: patch-embed GEMM  M=25088, N=384, K=768 ----------------
__global__ void __launch_bounds__(256) k1_patch_mma(
        const float* __restrict__ x,
        const float* __restrict__ convw,
        const float* __restrict__ convb,
        const float* __restrict__ pos) {
    __shared__ __nv_bfloat16 Ahi[128*SSTR], Alo[128*SSTR];
    __shared__ __nv_bfloat16 Bhi[128*SSTR], Blo[128*SSTR];

    int tid = threadIdx.x;
    int lane = tid & 31, warp = tid >> 5;
    int wm = warp & 1, wn = warp >> 1;            // 2 x 4 warp grid
    int tileM = blockIdx.x * 128;
    int tileN = blockIdx.y * 128;

    float acc[4][4][4] = {};

    // A gather geometry (rows fixed across chunks)
    int a_row[4], a_c4[4], a_base[4];
#pragma unroll
    for (int u = 0; u < 4; u++) {
        int idx = tid + 256*u;
        a_row[u] = idx >> 3; a_c4[u] = (idx & 7) * 4;
        int r = tileM + a_row[u];
        int b = r / NPATCH, p = r % NPATCH;
        int py = p / 14, px = p % 14;
        a_base[u] = b*(3*224*224) + (py*16)*224 + px*16;
    }

    float4 pa[4], pb[4];
    // prologue: chunk 0
#pragma unroll
    for (int u = 0; u < 4; u++) {
        int k = a_c4[u];
        int c = k >> 8, i = (k >> 4) & 15, j = k & 15;
        pa[u] = *(const float4*)&x[a_base[u] + c*50176 + i*224 + j];
        pb[u] = *(const float4*)&convw[(tileN + a_row[u])*768 + a_c4[u]];
    }

    for (int ch = 0; ch < 24; ch++) {
#pragma unroll
        for (int u = 0; u < 4; u++) {
            store_split4(Ahi, Alo, a_row[u], a_c4[u], pa[u]);
            store_split4(Bhi, Blo, a_row[u], a_c4[u], pb[u]);
        }
        __syncthreads();
        if (ch < 23) {
            int k0n = (ch+1) * 32;
#pragma unroll
            for (int u = 0; u < 4; u++) {
                int k = k0n + a_c4[u];
                int c = k >> 8, i = (k >> 4) & 15, j = k & 15;
                pa[u] = *(const float4*)&x[a_base[u] + c*50176 + i*224 + j];
                pb[u] = *(const float4*)&convw[(tileN + a_row[u])*768 + k];
            }
        }
#pragma unroll
        for (int kb = 0; kb < 32; kb += 16) {
            int kk = kb + (lane & 3)*2;
            uint32_t ah[4][4], al[4][4], bh[4][2], bl[4][2];
#pragma unroll
            for (int mf = 0; mf < 4; mf++) {
                int r0 = wm*64 + mf*16 + (lane >> 2);
                load_afrag(ah[mf], Ahi, r0, kk);
                load_afrag(al[mf], Alo, r0, kk);
            }
#pragma unroll
            for (int nf = 0; nf < 4; nf++) {
                int n0 = wn*32 + nf*8 + (lane >> 2);
                load_bfrag(bh[nf], Bhi, n0, kk);
                load_bfrag(bl[nf], Blo, n0, kk);
            }
#pragma unroll
            for (int mf = 0; mf < 4; mf++)
#pragma unroll
                for (int nf = 0; nf < 4; nf++) {
                    mma_bf16(acc[mf][nf], ah[mf], bh[nf]);
                    mma_bf16(acc[mf][nf], ah[mf], bl[nf]);
                    mma_bf16(acc[mf][nf], al[mf], bh[nf]);
                }
        }
        __syncthreads();
    }

    // epilogue: write with conv bias + pos embed, token remap
#pragma unroll
    for (int mf = 0; mf < 4; mf++) {
#pragma unroll
        for (int nf = 0; nf < 4; nf++) {
            int n = tileN + wn*32 + nf*8 + (lane & 3)*2;
            float cb0 = convb[n], cb1 = convb[n+1];
#pragma unroll
            for (int h = 0; h < 2; h++) {
                int R = tileM + wm*64 + mf*16 + (lane >> 2) + h*8;
                int b = R / NPATCH, p = R % NPATCH;
                int tok = b*NTOK + 1 + p;
                float2 o;
                o.x = acc[mf][nf][2*h]   + cb0 + pos[(1+p)*EMB + n];
                o.y = acc[mf][nf][2*h+1] + cb1 + pos[(1+p)*EMB + n + 1];
                *(float2*)&g_tok[tok*EMB + n] = o;
            }
        }
    }
}

// ---------------- K3: K/V projection GEMM  M=25216, N=768, K=384 ----------------
__global__ void __launch_bounds__(256) k3_kv_mma(
        const float* __restrict__ W, const float* __restrict__ bias) {
    __shared__ __nv_bfloat16 Ahi[128*SSTR], Alo[128*SSTR];
    __shared__ __nv_bfloat16 Bhi[128*SSTR], Blo[128*SSTR];

    int tid = threadIdx.x;
    int lane = tid & 31, warp = tid >> 5;
    int wm = warp & 1, wn = warp >> 1;
    int tileM = blockIdx.x * 128;
    int tileN = blockIdx.y * 128;

    float acc[4][4][4] = {};

    int row[4], c4[4];
#pragma unroll
    for (int u = 0; u < 4; u++) {
        int idx = tid + 256*u;
        row[u] = idx >> 3; c4[u] = (idx & 7) * 4;
    }

    float4 pa[4], pb[4];
#pragma unroll
    for (int u = 0; u < 4; u++) {
        pa[u] = *(const float4*)&g_hn[(tileM + row[u])*EMB + c4[u]];
        pb[u] = *(const float4*)&W[(384 + tileN + row[u])*EMB + c4[u]];
    }

    for (int ch = 0; ch < 12; ch++) {
#pragma unroll
        for (int u = 0; u < 4; u++) {
            store_split4(Ahi, Alo, row[u], c4[u], pa[u]);
            store_split4(Bhi, Blo, row[u], c4[u], pb[u]);
        }
        __syncthreads();
        if (ch < 11) {
            int k0n = (ch+1) * 32;
#pragma unroll
            for (int u = 0; u < 4; u++) {
                pa[u] = *(const float4*)&g_hn[(tileM + row[u])*EMB + k0n + c4[u]];
                pb[u] = *(const float4*)&W[(384 + tileN + row[u])*EMB + k0n + c4[u]];
            }
        }
#pragma unroll
        for (int kb = 0; kb < 32; kb += 16) {
            int kk = kb + (lane & 3)*2;
            uint32_t ah[4][4], al[4][4], bh[4][2], bl[4][2];
#pragma unroll
            for (int mf = 0; mf < 4; mf++) {
                int r0 = wm*64 + mf*16 + (lane >> 2);
                load_afrag(ah[mf], Ahi, r0, kk);
                load_afrag(al[mf], Alo, r0, kk);
            }
#pragma unroll
            for (int nf = 0; nf < 4; nf++) {
                int n0 = wn*32 + nf*8 + (lane >> 2);
                load_bfrag(bh[nf], Bhi, n0, kk);
                load_bfrag(bl[nf], Blo, n0, kk);
            }
#pragma unroll
            for (int mf = 0; mf < 4; mf++)
#pragma unroll
                for (int nf = 0; nf < 4; nf++) {
                    mma_bf16(acc[mf][nf], ah[mf], bh[nf]);
                    mma_bf16(acc[mf][nf], ah[mf], bl[nf]);
                    mma_bf16(acc[mf][nf], al[mf], bh[nf]);
                }
        }
        __syncthreads();
    }

#pragma unroll
    for (int mf = 0; mf < 4; mf++) {
#pragma unroll
        for (int nf = 0; nf < 4; nf++) {
            int n = tileN + wn*32 + nf*8 + (lane & 3)*2;
            float b0 = bias[384 + n], b1 = bias[384 + n + 1];
#pragma unroll
            for (int h = 0; h < 2; h++) {
                int R = tileM + wm*64 + mf*16 + (lane >> 2) + h*8;
                float2 o;
                o.x = acc[mf][nf][2*h]   + b0;
                o.y = acc[mf][nf][2*h+1] + b1;
                *(float2*)&g_kv[R*768 + n] = o;
            }
        }
    }
}

// ---------------- K2: LayerNorm over all tokens ----------------
__global__ void k2_ln(const float* __restrict__ g, const float* __restrict__ bt) {
    int t = blockIdx.x;
    const float* in  = g_tok + t*EMB;
    float*       out = g_hn  + t*EMB;
    int tid = threadIdx.x;                        // 128
    float x0 = in[tid], x1 = in[tid+128], x2 = in[tid+256];
    float s = x0+x1+x2, q = x0*x0 + x1*x1 + x2*x2;
    __shared__ float rs[4], rq[4];
    __shared__ float mm, rr;
    float ws = warp_sum(s), wq = warp_sum(q);
    int w = tid >> 5, l = tid & 31;
    if (l == 0) { rs[w] = ws; rq[w] = wq; }
    __syncthreads();
    if (tid == 0) {
        float S = rs[0]+rs[1]+rs[2]+rs[3];
        float Q = rq[0]+rq[1]+rq[2]+rq[3];
        float m = S * (1.0f/EMB);
        mm = m; rr = rsqrtf(Q*(1.0f/EMB) - m*m + 1e-5f);
    }
    __syncthreads();
    out[tid]     = (x0-mm)*rr*g[tid]     + bt[tid];
    out[tid+128] = (x1-mm)*rr*g[tid+128] + bt[tid+128];
    out[tid+256] = (x2-mm)*rr*g[tid+256] + bt[tid+256];
}

// ---------------- K4: q projection for cls rows only ----------------
__global__ void k4_q(const float* __restrict__ W, const float* __restrict__ bias) {
    int b = blockIdx.x;
    __shared__ float hs[EMB];
    int tid = threadIdx.x;                        // 256
    for (int e = tid; e < EMB; e += 256) hs[e] = g_hn[(b*NTOK)*EMB + e];
    __syncthreads();
    int w = tid >> 5, l = tid & 31;
    for (int o = w; o < EMB; o += 8) {
        float p = 0.f;
        for (int e = l; e < EMB; e += 32) p += hs[e]*W[o*EMB + e];
        p = warp_sum(p);
        if (l == 0) g_q[b*EMB + o] = p + bias[o];
    }
}

// ---------------- K5: attention for cls query ----------------
__global__ void k5_attn() {
    int bh = blockIdx.x;
    int b = bh / HEADS, h = bh % HEADS;
    int tid = threadIdx.x;                        // 256
    __shared__ float qs[HD];
    __shared__ float sc[NTOK];
    __shared__ float red[256];
    if (tid < HD) qs[tid] = g_q[b*EMB + h*HD + tid];
    __syncthreads();
    int w = tid >> 5, l = tid & 31;
    const float* kvb = g_kv + b*NTOK*768;
    for (int j = w; j < NTOK; j += 8) {
        const float* kr = kvb + j*768 + h*HD;
        float p = qs[l]*kr[l] + qs[l+32]*kr[l+32];
        p = warp_sum(p);
        if (l == 0) sc[j] = p * 0.125f;
    }
    __syncthreads();
    float mx = -1e30f;
    for (int j = tid; j < NTOK; j += 256) mx = fmaxf(mx, sc[j]);
    red[tid] = mx; __syncthreads();
    for (int s = 128; s > 0; s >>= 1) { if (tid < s) red[tid] = fmaxf(red[tid], red[tid+s]); __syncthreads(); }
    mx = red[0];
    __syncthreads();
    float sm = 0.f;
    for (int j = tid; j < NTOK; j += 256) { float e = expf(sc[j]-mx); sc[j] = e; sm += e; }
    red[tid] = sm; __syncthreads();
    for (int s = 128; s > 0; s >>= 1) { if (tid < s) red[tid] += red[tid+s]; __syncthreads(); }
    float inv = 1.0f / red[0];
    __syncthreads();
    int d = tid & 63, grp = tid >> 6;
    float acc = 0.f;
    for (int j = grp; j < NTOK; j += 4)
        acc += sc[j] * kvb[j*768 + 384 + h*HD + d];
    red[tid] = acc; __syncthreads();
    if (tid < HD) {
        float o = (red[tid] + red[tid+64] + red[tid+128] + red[tid+192]) * inv;
        g_att[b*EMB + h*HD + tid] = o;
    }
}

// ---------------- K6: out_proj + second LN (ln1 params) on cls rows ----------------
__global__ void k6_proj_ln(const float* __restrict__ W, const float* __restrict__ bias,
                           const float* __restrict__ g1, const float* __restrict__ b1) {
    int b = blockIdx.x;
    int tid = threadIdx.x;                        // 256
    __shared__ float as[EMB], pr[EMB];
    __shared__ float rs[8], rq[8];
    __shared__ float mm, rr;
    for (int e = tid; e < EMB; e += 256) as[e] = g_att[b*EMB + e];
    __syncthreads();
    int w = tid >> 5, l = tid & 31;
    for (int o = w; o < EMB; o += 8) {
        float p = 0.f;
        for (int e = l; e < EMB; e += 32) p += as[e]*W[o*EMB + e];
        p = warp_sum(p);
        if (l == 0) pr[o] = p + bias[o];
    }
    __syncthreads();
    float s = 0.f, q = 0.f;
    for (int e = tid; e < EMB; e += 256) { float v = pr[e]; s += v; q += v*v; }
    s = warp_sum(s); q = warp_sum(q);
    if (l == 0) { rs[w] = s; rq[w] = q; }
    __syncthreads();
    if (tid == 0) {
        float S = 0.f, Q = 0.f;
        for (int i = 0; i < 8; i++) { S += rs[i]; Q += rq[i]; }
        float m = S*(1.0f/EMB);
        mm = m; rr = rsqrtf(Q*(1.0f/EMB) - m*m + 1e-5f);
    }
    __syncthreads();
    for (int e = tid; e < EMB; e += 256)
        g_h2[b*EMB + e] = (pr[e]-mm)*rr*g1[e] + b1[e];
}

// ---------------- K7: router + top-2 ----------------
__global__ void k7_router(const float* __restrict__ W, const float* __restrict__ bias) {
    int b = blockIdx.x;
    int tid = threadIdx.x;                        // 128
    __shared__ float hs[EMB];
    __shared__ float lg[NE];
    for (int e = tid; e < EMB; e += 128) hs[e] = g_h2[b*EMB + e];
    __syncthreads();
    int w = tid >> 5, l = tid & 31;
    if (w < NE) {
        float p = 0.f;
        for (int e = l; e < EMB; e += 32) p += hs[e]*W[w*EMB + e];
        p = warp_sum(p);
        if (l == 0) lg[w] = p + bias[w];
    }
    __syncthreads();
    if (tid == 0) {
        int i1 = 0;
        for (int i = 1; i < NE; i++) if (lg[i] > lg[i1]) i1 = i;
        int i2 = -1;
        for (int i = 0; i < NE; i++) {
            if (i == i1) continue;
            if (i2 < 0 || lg[i] > lg[i2]) i2 = i;
        }
        g_topk[b*2]   = i1;
        g_topk[b*2+1] = i2;
    }
}

// ---------------- K7b: build per-expert entry lists (single block) ----------------
__global__ void k7b_build() {
    __shared__ int cnt[NE];
    int tid = threadIdx.x;                        // 256
    if (tid < NE) cnt[tid] = 0;
    __syncthreads();
    int e = g_topk[tid];                          // entry = tid = b*2+slot
    int pos = atomicAdd(&cnt[e], 1);
    g_elist[e*256 + pos] = tid;
    __syncthreads();
    if (tid < NE) g_ecnt[tid] = cnt[tid];
}

// ---------------- K8: MoE expert FFN, expert-grouped, 4 tokens/block ----------------
#define MOE_TOK 4
__global__ void __launch_bounds__(384) k8_moe(
        const float* __restrict__ ew1, const float* __restrict__ eb1,
        const float* __restrict__ ew2, const float* __restrict__ eb2) {
    int e = blockIdx.x;
    int tile = blockIdx.y;
    int n = g_ecnt[e];
    int t0 = tile * MOE_TOK;
    if (t0 >= n) return;
    int nt = min(MOE_TOK, n - t0);

    __shared__ float hs[MOE_TOK][EMB];
    __shared__ float hid[MOE_TOK][HID];
    __shared__ int ent[MOE_TOK];

    int tid = threadIdx.x;                        // 384
    if (tid < MOE_TOK)
        ent[tid] = g_elist[e*256 + t0 + ((tid < nt) ? tid : 0)];
    __syncthreads();
#pragma unroll
    for (int tt = 0; tt < MOE_TOK; tt++)
        hs[tt][tid] = g_h2[(ent[tt] >> 1)*EMB + tid];
    __syncthreads();

    int c0 = tid * 4;
    const float* W1 = ew1 + (size_t)e*EMB*HID;
    float4 b14 = *(const float4*)&eb1[e*HID + c0];
    float acc[MOE_TOK][4];
#pragma unroll
    for (int tt = 0; tt < MOE_TOK; tt++) {
        acc[tt][0] = b14.x; acc[tt][1] = b14.y; acc[tt][2] = b14.z; acc[tt][3] = b14.w;
    }
    for (int k = 0; k < EMB; k++) {
        float4 w = *(const float4*)&W1[(size_t)k*HID + c0];
#pragma unroll
        for (int tt = 0; tt < MOE_TOK; tt++) {
            float hv = hs[tt][k];
            acc[tt][0] += hv*w.x; acc[tt][1] += hv*w.y;
            acc[tt][2] += hv*w.z; acc[tt][3] += hv*w.w;
        }
    }
#pragma unroll
    for (int tt = 0; tt < MOE_TOK; tt++) {
        hid[tt][c0+0] = gelu_exact(acc[tt][0]);
        hid[tt][c0+1] = gelu_exact(acc[tt][1]);
        hid[tt][c0+2] = gelu_exact(acc[tt][2]);
        hid[tt][c0+3] = gelu_exact(acc[tt][3]);
    }
    __syncthreads();

    const float* W2 = ew2 + (size_t)e*HID*EMB;
    float oacc[MOE_TOK] = {};
    for (int k = 0; k < HID; k++) {
        float w = W2[(size_t)k*EMB + tid];
#pragma unroll
        for (int tt = 0; tt < MOE_TOK; tt++)
            oacc[tt] += hid[tt][k] * w;
    }
    float b2v = eb2[e*EMB + tid];
#pragma unroll
    for (int tt = 0; tt < MOE_TOK; tt++) {
        if (tt < nt)
            g_moepart[ent[tt]*EMB + tid] = 0.5f * (oacc[tt] + b2v);
    }
}

// ---------------- K9: LN2 + classification head on cls tokens ----------------
__global__ void k9_head(const float* __restrict__ g2, const float* __restrict__ b2,
                        const float* __restrict__ Wh, const float* __restrict__ bh,
                        float* __restrict__ out) {
    int b = blockIdx.x;
    int tid = threadIdx.x;                        // 256
    __shared__ float hs[EMB], hl[EMB];
    __shared__ float rs[8], rq[8];
    __shared__ float mm, rr;
    for (int e = tid; e < EMB; e += 256)
        hs[e] = g_moepart[(b*2)*EMB + e] + g_moepart[(b*2+1)*EMB + e];
    __syncthreads();
    float s = 0.f, q = 0.f;
    for (int e = tid; e < EMB; e += 256) { float v = hs[e]; s += v; q += v*v; }
    s = warp_sum(s); q = warp_sum(q);
    int w = tid >> 5, l = tid & 31;
    if (l == 0) { rs[w] = s; rq[w] = q; }
    __syncthreads();
    if (tid == 0) {
        float S = 0.f, Q = 0.f;
        for (int i = 0; i < 8; i++) { S += rs[i]; Q += rq[i]; }
        float m = S*(1.0f/EMB);
        mm = m; rr = rsqrtf(Q*(1.0f/EMB) - m*m + 1e-5f);
    }
    __syncthreads();
    for (int e = tid; e < EMB; e += 256) hl[e] = (hs[e]-mm)*rr*g2[e] + b2[e];
    __syncthreads();
    for (int it = 0; it < 125; it++) {
        int c = w + 8*it;
        float p = 0.f;
        for (int e = l; e < EMB; e += 32) p += hl[e]*Wh[c*EMB + e];
        p = warp_sum(p);
        if (l == 0) out[b*NCLS + c] = p + bh[c];
    }
}

// ---------------- launcher ----------------
extern "C" void kernel_launch(void* const* d_in, const int* in_sizes, int n_in,
                              void* d_out, int out_size) {
    const float* x         = (const float*)d_in[0];
    const float* conv_w    = (const float*)d_in[1];
    const float* conv_b    = (const float*)d_in[2];
    const float* cls_token = (const float*)d_in[3];
    const float* pos_embed = (const float*)d_in[4];
    const float* ln1_g     = (const float*)d_in[5];
    const float* ln1_b     = (const float*)d_in[6];
    const float* in_proj_w = (const float*)d_in[7];
    const float* in_proj_b = (const float*)d_in[8];
    const float* out_proj_w= (const float*)d_in[9];
    const float* out_proj_b= (const float*)d_in[10];
    const float* router_w  = (const float*)d_in[11];
    const float* router_b  = (const float*)d_in[12];
    const float* ew1       = (const float*)d_in[13];
    const float* eb1       = (const float*)d_in[14];
    const float* ew2       = (const float*)d_in[15];
    const float* eb2       = (const float*)d_in[16];
    const float* ln2_g     = (const float*)d_in[17];
    const float* ln2_b     = (const float*)d_in[18];
    const float* head_w    = (const float*)d_in[19];
    const float* head_b    = (const float*)d_in[20];
    float* out = (float*)d_out;

    k0_cls<<<BATCH, EMB>>>(cls_token, pos_embed);
    k1_patch_mma<<<dim3(MPATCH/128, EMB/128), 256>>>(x, conv_w, conv_b, pos_embed);
    k2_ln<<<MTOK, 128>>>(ln1_g, ln1_b);
    k3_kv_mma<<<dim3(MTOK/128, 768/128), 256>>>(in_proj_w, in_proj_b);
    k4_q<<<BATCH, 256>>>(in_proj_w, in_proj_b);
    k5_attn<<<BATCH*HEADS, 256>>>();
    k6_proj_ln<<<BATCH, 256>>>(out_proj_w, out_proj_b, ln1_g, ln1_b);
    k7_router<<<BATCH, 128>>>(router_w, router_b);
    k7b_build<<<1, 256>>>();
    k8_moe<<<dim3(NE, 256/MOE_TOK), 384>>>(ew1, eb1, ew2, eb2);
    k9_head<<<BATCH, 256>>>(ln2_g, ln2_b, head_w, head_b, out);
}

// round 5
// speedup vs baseline: 2.8016x; 1.1995x over previous
#include <cuda_runtime.h>
#include <cuda_bf16.h>
#include <math.h>
#include <stdint.h>

// ---------------- problem constants ----------------
#define BATCH 128
#define EMB   384
#define NTOK  197
#define NPATCH 196
#define HEADS 6
#define HD    64
#define HID   1536
#define NE    4
#define NCLS  1000
#define MTOK  (BATCH*NTOK)      // 25216 = 197*128
#define MPATCH (BATCH*NPATCH)   // 25088 = 196*128
#define SSTR  40                // smem row stride in bf16 halves (conflict-free)
#define TSZ   (128*SSTR)        // one tile buffer in halves (5120)
#define SMEM_GEMM (8*TSZ*2)     // 8 buffers (4 arrays x 2 stages) = 81920 B

// ---------------- scratch (static device globals; no allocation) ----------------
__device__ float g_tok[MTOK*EMB];
__device__ float g_hn [MTOK*EMB];
__device__ float g_kv [MTOK*768];
__device__ float g_q  [BATCH*EMB];
__device__ float g_att[BATCH*EMB];
__device__ float g_h2 [BATCH*EMB];
__device__ float g_moepart[BATCH*2*EMB];
__device__ int   g_topk[BATCH*2];
__device__ int   g_ecnt[NE];
__device__ int   g_elist[NE*256];

__device__ __forceinline__ float warp_sum(float v) {
#pragma unroll
    for (int o = 16; o > 0; o >>= 1) v += __shfl_down_sync(0xffffffffu, v, o);
    return v;
}
__device__ __forceinline__ float gelu_exact(float v) {
    return 0.5f * v * (1.0f + erff(v * 0.70710678118654752f));
}

// mma.sync m16n8k16 bf16 -> f32 (legacy HMMA; works on plain sm_103 target)
__device__ __forceinline__ void mma_bf16(float* c, const uint32_t* a, const uint32_t* b) {
    asm volatile(
        "mma.sync.aligned.m16n8k16.row.col.f32.bf16.bf16.f32 "
        "{%0,%1,%2,%3}, {%4,%5,%6,%7}, {%8,%9}, {%0,%1,%2,%3};"
        : "+f"(c[0]), "+f"(c[1]), "+f"(c[2]), "+f"(c[3])
        : "r"(a[0]), "r"(a[1]), "r"(a[2]), "r"(a[3]), "r"(b[0]), "r"(b[1]));
}

// split fp32x4 -> bf16 hi/lo, store 4 halves (8B) to smem at [row][c4]
__device__ __forceinline__ void store_split4(__nv_bfloat16* hiB, __nv_bfloat16* loB,
                                             int row, int c4, float4 v) {
    __nv_bfloat16 h0 = __float2bfloat16_rn(v.x);
    __nv_bfloat16 h1 = __float2bfloat16_rn(v.y);
    __nv_bfloat16 h2 = __float2bfloat16_rn(v.z);
    __nv_bfloat16 h3 = __float2bfloat16_rn(v.w);
    __nv_bfloat16 l0 = __float2bfloat16_rn(v.x - __bfloat162float(h0));
    __nv_bfloat16 l1 = __float2bfloat16_rn(v.y - __bfloat162float(h1));
    __nv_bfloat16 l2 = __float2bfloat16_rn(v.z - __bfloat162float(h2));
    __nv_bfloat16 l3 = __float2bfloat16_rn(v.w - __bfloat16_as_ushort(h3) * 0.0f - __bfloat162float(h3));
    uint2 hp, lp;
    hp.x = ((uint32_t)__bfloat16_as_ushort(h1) << 16) | __bfloat16_as_ushort(h0);
    hp.y = ((uint32_t)__bfloat16_as_ushort(h3) << 16) | __bfloat16_as_ushort(h2);
    lp.x = ((uint32_t)__bfloat16_as_ushort(l1) << 16) | __bfloat16_as_ushort(l0);
    lp.y = ((uint32_t)__bfloat16_as_ushort(l3) << 16) | __bfloat16_as_ushort(l2);
    *(uint2*)&hiB[row*SSTR + c4] = hp;
    *(uint2*)&loB[row*SSTR + c4] = lp;
}

__device__ __forceinline__ void load_afrag(uint32_t* a, const __nv_bfloat16* S, int r0, int kk) {
    a[0] = *(const uint32_t*)&S[(r0    )*SSTR + kk    ];
    a[1] = *(const uint32_t*)&S[(r0 + 8)*SSTR + kk    ];
    a[2] = *(const uint32_t*)&S[(r0    )*SSTR + kk + 8];
    a[3] = *(const uint32_t*)&S[(r0 + 8)*SSTR + kk + 8];
}
__device__ __forceinline__ void load_bfrag(uint32_t* b, const __nv_bfloat16* S, int n0, int kk) {
    b[0] = *(const uint32_t*)&S[n0*SSTR + kk    ];
    b[1] = *(const uint32_t*)&S[n0*SSTR + kk + 8];
}

// ---------------- K0: cls token row init ----------------
__global__ void k0_cls(const float* __restrict__ cls, const float* __restrict__ pos) {
    int b = blockIdx.x;
    int e = threadIdx.x;
    g_tok[(b*NTOK)*EMB + e] = cls[e] + pos[e];
}

// ============ HMMA GEMM: block 128x128, 8 warps (64x32), K-chunk 32, split-bf16, 2-stage ======

// ---------------- K1: patch-embed GEMM  M=25088, N=384, K=768 ----------------
__global__ void __launch_bounds__(256) k1_patch_mma(
        const float* __restrict__ x,
        const float* __restrict__ convw,
        const float* __restrict__ convb,
        const float* __restrict__ pos) {
    extern __shared__ __nv_bfloat16 sm[];
    int tid = threadIdx.x;
    int lane = tid & 31, warp = tid >> 5;
    int wm = warp & 1, wn = warp >> 1;            // 2 x 4 warp grid
    int tileM = blockIdx.x * 128;
    int tileN = blockIdx.y * 128;

    float acc[4][4][4] = {};

    int a_row[4], a_c4[4], a_base[4];
#pragma unroll
    for (int u = 0; u < 4; u++) {
        int idx = tid + 256*u;
        a_row[u] = idx >> 3; a_c4[u] = (idx & 7) * 4;
        int r = tileM + a_row[u];
        int b = r / NPATCH, p = r % NPATCH;
        int py = p / 14, px = p % 14;
        a_base[u] = b*(3*224*224) + (py*16)*224 + px*16;
    }

    float4 pa[4], pb[4];
#pragma unroll
    for (int u = 0; u < 4; u++) {
        int k = a_c4[u];
        int c = k >> 8, i = (k >> 4) & 15, j = k & 15;
        pa[u] = *(const float4*)&x[a_base[u] + c*50176 + i*224 + j];
        pb[u] = *(const float4*)&convw[(tileN + a_row[u])*768 + a_c4[u]];
    }
    {   // store chunk 0 into stage 0
        __nv_bfloat16 *A_h = sm, *A_l = sm + 2*TSZ, *B_h = sm + 4*TSZ, *B_l = sm + 6*TSZ;
#pragma unroll
        for (int u = 0; u < 4; u++) {
            store_split4(A_h, A_l, a_row[u], a_c4[u], pa[u]);
            store_split4(B_h, B_l, a_row[u], a_c4[u], pb[u]);
        }
    }
    __syncthreads();

    for (int ch = 0; ch < 24; ch++) {
        int cur = ch & 1, nxt = cur ^ 1;
        __nv_bfloat16 *cAh = sm + cur*TSZ,       *cAl = sm + (2+cur)*TSZ;
        __nv_bfloat16 *cBh = sm + (4+cur)*TSZ,   *cBl = sm + (6+cur)*TSZ;
        if (ch < 23) {
            int k0n = (ch+1) * 32;
#pragma unroll
            for (int u = 0; u < 4; u++) {
                int k = k0n + a_c4[u];
                int c = k >> 8, i = (k >> 4) & 15, j = k & 15;
                pa[u] = *(const float4*)&x[a_base[u] + c*50176 + i*224 + j];
                pb[u] = *(const float4*)&convw[(tileN + a_row[u])*768 + k];
            }
        }
#pragma unroll
        for (int kb = 0; kb < 32; kb += 16) {
            int kk = kb + (lane & 3)*2;
            uint32_t ah[4][4], al[4][4], bh[4][2], bl[4][2];
#pragma unroll
            for (int mf = 0; mf < 4; mf++) {
                int r0 = wm*64 + mf*16 + (lane >> 2);
                load_afrag(ah[mf], cAh, r0, kk);
                load_afrag(al[mf], cAl, r0, kk);
            }
#pragma unroll
            for (int nf = 0; nf < 4; nf++) {
                int n0 = wn*32 + nf*8 + (lane >> 2);
                load_bfrag(bh[nf], cBh, n0, kk);
                load_bfrag(bl[nf], cBl, n0, kk);
            }
#pragma unroll
            for (int mf = 0; mf < 4; mf++)
#pragma unroll
                for (int nf = 0; nf < 4; nf++)
                    mma_bf16(acc[mf][nf], ah[mf], bh[nf]);
#pragma unroll
            for (int mf = 0; mf < 4; mf++)
#pragma unroll
                for (int nf = 0; nf < 4; nf++)
                    mma_bf16(acc[mf][nf], ah[mf], bl[nf]);
#pragma unroll
            for (int mf = 0; mf < 4; mf++)
#pragma unroll
                for (int nf = 0; nf < 4; nf++)
                    mma_bf16(acc[mf][nf], al[mf], bh[nf]);
        }
        if (ch < 23) {
            __nv_bfloat16 *nAh = sm + nxt*TSZ,     *nAl = sm + (2+nxt)*TSZ;
            __nv_bfloat16 *nBh = sm + (4+nxt)*TSZ, *nBl = sm + (6+nxt)*TSZ;
#pragma unroll
            for (int u = 0; u < 4; u++) {
                store_split4(nAh, nAl, a_row[u], a_c4[u], pa[u]);
                store_split4(nBh, nBl, a_row[u], a_c4[u], pb[u]);
            }
        }
        __syncthreads();
    }

#pragma unroll
    for (int mf = 0; mf < 4; mf++) {
#pragma unroll
        for (int nf = 0; nf < 4; nf++) {
            int n = tileN + wn*32 + nf*8 + (lane & 3)*2;
            float cb0 = convb[n], cb1 = convb[n+1];
#pragma unroll
            for (int h = 0; h < 2; h++) {
                int R = tileM + wm*64 + mf*16 + (lane >> 2) + h*8;
                int b = R / NPATCH, p = R % NPATCH;
                int tok = b*NTOK + 1 + p;
                float2 o;
                o.x = acc[mf][nf][2*h]   + cb0 + pos[(1+p)*EMB + n];
                o.y = acc[mf][nf][2*h+1] + cb1 + pos[(1+p)*EMB + n + 1];
                *(float2*)&g_tok[tok*EMB + n] = o;
            }
        }
    }
}

// ---------------- K3: K/V projection GEMM  M=25216, N=768, K=384 ----------------
__global__ void __launch_bounds__(256) k3_kv_mma(
        const float* __restrict__ W, const float* __restrict__ bias) {
    extern __shared__ __nv_bfloat16 sm[];
    int tid = threadIdx.x;
    int lane = tid & 31, warp = tid >> 5;
    int wm = warp & 1, wn = warp >> 1;
    int tileM = blockIdx.x * 128;
    int tileN = blockIdx.y * 128;

    float acc[4][4][4] = {};

    int row[4], c4[4];
#pragma unroll
    for (int u = 0; u < 4; u++) {
        int idx = tid + 256*u;
        row[u] = idx >> 3; c4[u] = (idx & 7) * 4;
    }

    float4 pa[4], pb[4];
#pragma unroll
    for (int u = 0; u < 4; u++) {
        pa[u] = *(const float4*)&g_hn[(tileM + row[u])*EMB + c4[u]];
        pb[u] = *(const float4*)&W[(384 + tileN + row[u])*EMB + c4[u]];
    }
    {
        __nv_bfloat16 *A_h = sm, *A_l = sm + 2*TSZ, *B_h = sm + 4*TSZ, *B_l = sm + 6*TSZ;
#pragma unroll
        for (int u = 0; u < 4; u++) {
            store_split4(A_h, A_l, row[u], c4[u], pa[u]);
            store_split4(B_h, B_l, row[u], c4[u], pb[u]);
        }
    }
    __syncthreads();

    for (int ch = 0; ch < 12; ch++) {
        int cur = ch & 1, nxt = cur ^ 1;
        __nv_bfloat16 *cAh = sm + cur*TSZ,       *cAl = sm + (2+cur)*TSZ;
        __nv_bfloat16 *cBh = sm + (4+cur)*TSZ,   *cBl = sm + (6+cur)*TSZ;
        if (ch < 11) {
            int k0n = (ch+1) * 32;
#pragma unroll
            for (int u = 0; u < 4; u++) {
                pa[u] = *(const float4*)&g_hn[(tileM + row[u])*EMB + k0n + c4[u]];
                pb[u] = *(const float4*)&W[(384 + tileN + row[u])*EMB + k0n + c4[u]];
            }
        }
#pragma unroll
        for (int kb = 0; kb < 32; kb += 16) {
            int kk = kb + (lane & 3)*2;
            uint32_t ah[4][4], al[4][4], bh[4][2], bl[4][2];
#pragma unroll
            for (int mf = 0; mf < 4; mf++) {
                int r0 = wm*64 + mf*16 + (lane >> 2);
                load_afrag(ah[mf], cAh, r0, kk);
                load_afrag(al[mf], cAl, r0, kk);
            }
#pragma unroll
            for (int nf = 0; nf < 4; nf++) {
                int n0 = wn*32 + nf*8 + (lane >> 2);
                load_bfrag(bh[nf], cBh, n0, kk);
                load_bfrag(bl[nf], cBl, n0, kk);
            }
#pragma unroll
            for (int mf = 0; mf < 4; mf++)
#pragma unroll
                for (int nf = 0; nf < 4; nf++)
                    mma_bf16(acc[mf][nf], ah[mf], bh[nf]);
#pragma unroll
            for (int mf = 0; mf < 4; mf++)
#pragma unroll
                for (int nf = 0; nf < 4; nf++)
                    mma_bf16(acc[mf][nf], ah[mf], bl[nf]);
#pragma unroll
            for (int mf = 0; mf < 4; mf++)
#pragma unroll
                for (int nf = 0; nf < 4; nf++)
                    mma_bf16(acc[mf][nf], al[mf], bh[nf]);
        }
        if (ch < 11) {
            __nv_bfloat16 *nAh = sm + nxt*TSZ,     *nAl = sm + (2+nxt)*TSZ;
            __nv_bfloat16 *nBh = sm + (4+nxt)*TSZ, *nBl = sm + (6+nxt)*TSZ;
#pragma unroll
            for (int u = 0; u < 4; u++) {
                store_split4(nAh, nAl, row[u], c4[u], pa[u]);
                store_split4(nBh, nBl, row[u], c4[u], pb[u]);
            }
        }
        __syncthreads();
    }

#pragma unroll
    for (int mf = 0; mf < 4; mf++) {
#pragma unroll
        for (int nf = 0; nf < 4; nf++) {
            int n = tileN + wn*32 + nf*8 + (lane & 3)*2;
            float b0 = bias[384 + n], b1 = bias[384 + n + 1];
#pragma unroll
            for (int h = 0; h < 2; h++) {
                int R = tileM + wm*64 + mf*16 + (lane >> 2) + h*8;
                float2 o;
                o.x = acc[mf][nf][2*h]   + b0;
                o.y = acc[mf][nf][2*h+1] + b1;
                *(float2*)&g_kv[R*768 + n] = o;
            }
        }
    }
}

// ---------------- K2: LayerNorm over all tokens ----------------
__global__ void k2_ln(const float* __restrict__ g, const float* __restrict__ bt) {
    int t = blockIdx.x;
    const float* in  = g_tok + t*EMB;
    float*       out = g_hn  + t*EMB;
    int tid = threadIdx.x;                        // 128
    float x0 = in[tid], x1 = in[tid+128], x2 = in[tid+256];
    float s = x0+x1+x2, q = x0*x0 + x1*x1 + x2*x2;
    __shared__ float rs[4], rq[4];
    __shared__ float mm, rr;
    float ws = warp_sum(s), wq = warp_sum(q);
    int w = tid >> 5, l = tid & 31;
    if (l == 0) { rs[w] = ws; rq[w] = wq; }
    __syncthreads();
    if (tid == 0) {
        float S = rs[0]+rs[1]+rs[2]+rs[3];
        float Q = rq[0]+rq[1]+rq[2]+rq[3];
        float m = S * (1.0f/EMB);
        mm = m; rr = rsqrtf(Q*(1.0f/EMB) - m*m + 1e-5f);
    }
    __syncthreads();
    out[tid]     = (x0-mm)*rr*g[tid]     + bt[tid];
    out[tid+128] = (x1-mm)*rr*g[tid+128] + bt[tid+128];
    out[tid+256] = (x2-mm)*rr*g[tid+256] + bt[tid+256];
}

// ---------------- K4: q projection, thread-per-output ----------------
__global__ void __launch_bounds__(EMB) k4_q(const float* __restrict__ W,
                                            const float* __restrict__ bias) {
    int b = blockIdx.x;
    int tid = threadIdx.x;                        // 384
    __shared__ float hs[EMB];
    hs[tid] = g_hn[(b*NTOK)*EMB + tid];
    __syncthreads();
    float acc = bias[tid];
    const float4* Wr = (const float4*)(W + (size_t)tid*EMB);
#pragma unroll 8
    for (int k = 0; k < 96; k++) {
        float4 w = Wr[k];
        acc += hs[4*k]*w.x + hs[4*k+1]*w.y + hs[4*k+2]*w.z + hs[4*k+3]*w.w;
    }
    g_q[b*EMB + tid] = acc;
}

// ---------------- K5: attention for cls query ----------------
__global__ void k5_attn() {
    int bh = blockIdx.x;
    int b = bh / HEADS, h = bh % HEADS;
    int tid = threadIdx.x;                        // 256
    __shared__ float qs[HD];
    __shared__ float sc[NTOK];
    __shared__ float red[256];
    if (tid < HD) qs[tid] = g_q[b*EMB + h*HD + tid];
    __syncthreads();
    const float* kvb = g_kv + b*NTOK*768;
    if (tid < NTOK) {
        const float4* kr = (const float4*)(kvb + tid*768 + h*HD);
        float p = 0.f;
#pragma unroll
        for (int d = 0; d < 16; d++) {
            float4 kv4 = kr[d];
            p += qs[4*d]*kv4.x + qs[4*d+1]*kv4.y + qs[4*d+2]*kv4.z + qs[4*d+3]*kv4.w;
        }
        sc[tid] = p * 0.125f;
    }
    __syncthreads();
    float mx = -1e30f;
    for (int j = tid; j < NTOK; j += 256) mx = fmaxf(mx, sc[j]);
    red[tid] = mx; __syncthreads();
    for (int s = 128; s > 0; s >>= 1) { if (tid < s) red[tid] = fmaxf(red[tid], red[tid+s]); __syncthreads(); }
    mx = red[0];
    __syncthreads();
    float sm = 0.f;
    for (int j = tid; j < NTOK; j += 256) { float e = expf(sc[j]-mx); sc[j] = e; sm += e; }
    red[tid] = sm; __syncthreads();
    for (int s = 128; s > 0; s >>= 1) { if (tid < s) red[tid] += red[tid+s]; __syncthreads(); }
    float inv = 1.0f / red[0];
    __syncthreads();
    int d = tid & 63, grp = tid >> 6;
    float acc = 0.f;
    for (int j = grp; j < NTOK; j += 4)
        acc += sc[j] * kvb[j*768 + 384 + h*HD + d];
    red[tid] = acc; __syncthreads();
    if (tid < HD) {
        float o = (red[tid] + red[tid+64] + red[tid+128] + red[tid+192]) * inv;
        g_att[b*EMB + h*HD + tid] = o;
    }
}

// ---------------- K6: out_proj + second LN, thread-per-output ----------------
__global__ void __launch_bounds__(EMB) k6_proj_ln(
        const float* __restrict__ W, const float* __restrict__ bias,
        const float* __restrict__ g1, const float* __restrict__ b1) {
    int b = blockIdx.x;
    int tid = threadIdx.x;                        // 384 = 12 warps
    __shared__ float as[EMB];
    __shared__ float rs[12], rq[12];
    __shared__ float mm, rr;
    as[tid] = g_att[b*EMB + tid];
    __syncthreads();
    float acc = bias[tid];
    const float4* Wr = (const float4*)(W + (size_t)tid*EMB);
#pragma unroll 8
    for (int k = 0; k < 96; k++) {
        float4 w = Wr[k];
        acc += as[4*k]*w.x + as[4*k+1]*w.y + as[4*k+2]*w.z + as[4*k+3]*w.w;
    }
    // LN over the 384 acc values
    float s = warp_sum(acc), q = warp_sum(acc*acc);
    int w = tid >> 5, l = tid & 31;
    if (l == 0) { rs[w] = s; rq[w] = q; }
    __syncthreads();
    if (tid == 0) {
        float S = 0.f, Q = 0.f;
#pragma unroll
        for (int i = 0; i < 12; i++) { S += rs[i]; Q += rq[i]; }
        float m = S*(1.0f/EMB);
        mm = m; rr = rsqrtf(Q*(1.0f/EMB) - m*m + 1e-5f);
    }
    __syncthreads();
    g_h2[b*EMB + tid] = (acc-mm)*rr*g1[tid] + b1[tid];
}

// ---------------- K7: router + top-2 ----------------
__global__ void k7_router(const float* __restrict__ W, const float* __restrict__ bias) {
    int b = blockIdx.x;
    int tid = threadIdx.x;                        // 128
    __shared__ float hs[EMB];
    __shared__ float lg[NE];
    for (int e = tid; e < EMB; e += 128) hs[e] = g_h2[b*EMB + e];
    __syncthreads();
    int w = tid >> 5, l = tid & 31;
    if (w < NE) {
        float p = 0.f;
        for (int e = l; e < EMB; e += 32) p += hs[e]*W[w*EMB + e];
        p = warp_sum(p);
        if (l == 0) lg[w] = p + bias[w];
    }
    __syncthreads();
    if (tid == 0) {
        int i1 = 0;
        for (int i = 1; i < NE; i++) if (lg[i] > lg[i1]) i1 = i;
        int i2 = -1;
        for (int i = 0; i < NE; i++) {
            if (i == i1) continue;
            if (i2 < 0 || lg[i] > lg[i2]) i2 = i;
        }
        g_topk[b*2]   = i1;
        g_topk[b*2+1] = i2;
    }
}

// ---------------- K7b: build per-expert entry lists (single block) ----------------
__global__ void k7b_build() {
    __shared__ int cnt[NE];
    int tid = threadIdx.x;                        // 256
    if (tid < NE) cnt[tid] = 0;
    __syncthreads();
    int e = g_topk[tid];
    int pos = atomicAdd(&cnt[e], 1);
    g_elist[e*256 + pos] = tid;
    __syncthreads();
    if (tid < NE) g_ecnt[tid] = cnt[tid];
}

// ---------------- K8: MoE expert FFN, expert-grouped, 4 tokens/block ----------------
#define MOE_TOK 4
__global__ void __launch_bounds__(384) k8_moe(
        const float* __restrict__ ew1, const float* __restrict__ eb1,
        const float* __restrict__ ew2, const float* __restrict__ eb2) {
    int e = blockIdx.x;
    int tile = blockIdx.y;
    int n = g_ecnt[e];
    int t0 = tile * MOE_TOK;
    if (t0 >= n) return;
    int nt = min(MOE_TOK, n - t0);

    __shared__ float hs[MOE_TOK][EMB];
    __shared__ float hid[MOE_TOK][HID];
    __shared__ int ent[MOE_TOK];

    int tid = threadIdx.x;                        // 384
    if (tid < MOE_TOK)
        ent[tid] = g_elist[e*256 + t0 + ((tid < nt) ? tid : 0)];
    __syncthreads();
#pragma unroll
    for (int tt = 0; tt < MOE_TOK; tt++)
        hs[tt][tid] = g_h2[(ent[tt] >> 1)*EMB + tid];
    __syncthreads();

    int c0 = tid * 4;
    const float* W1 = ew1 + (size_t)e*EMB*HID;
    float4 b14 = *(const float4*)&eb1[e*HID + c0];
    float acc[MOE_TOK][4];
#pragma unroll
    for (int tt = 0; tt < MOE_TOK; tt++) {
        acc[tt][0] = b14.x; acc[tt][1] = b14.y; acc[tt][2] = b14.z; acc[tt][3] = b14.w;
    }
    for (int k = 0; k < EMB; k++) {
        float4 w = *(const float4*)&W1[(size_t)k*HID + c0];
#pragma unroll
        for (int tt = 0; tt < MOE_TOK; tt++) {
            float hv = hs[tt][k];
            acc[tt][0] += hv*w.x; acc[tt][1] += hv*w.y;
            acc[tt][2] += hv*w.z; acc[tt][3] += hv*w.w;
        }
    }
#pragma unroll
    for (int tt = 0; tt < MOE_TOK; tt++) {
        hid[tt][c0+0] = gelu_exact(acc[tt][0]);
        hid[tt][c0+1] = gelu_exact(acc[tt][1]);
        hid[tt][c0+2] = gelu_exact(acc[tt][2]);
        hid[tt][c0+3] = gelu_exact(acc[tt][3]);
    }
    __syncthreads();

    const float* W2 = ew2 + (size_t)e*HID*EMB;
    float oacc[MOE_TOK] = {};
    for (int k = 0; k < HID; k++) {
        float w = W2[(size_t)k*EMB + tid];
#pragma unroll
        for (int tt = 0; tt < MOE_TOK; tt++)
            oacc[tt] += hid[tt][k] * w;
    }
    float b2v = eb2[e*EMB + tid];
#pragma unroll
    for (int tt = 0; tt < MOE_TOK; tt++) {
        if (tt < nt)
            g_moepart[ent[tt]*EMB + tid] = 0.5f * (oacc[tt] + b2v);
    }
}

// ---------------- K9: LN2 + classification head, thread-per-col ----------------
__global__ void __launch_bounds__(EMB) k9_head(
        const float* __restrict__ g2, const float* __restrict__ b2,
        const float* __restrict__ Wh, const float* __restrict__ bh,
        float* __restrict__ out) {
    int b = blockIdx.x;
    int tid = threadIdx.x;                        // 384
    __shared__ float hl[EMB];
    __shared__ float rs[12], rq[12];
    __shared__ float mm, rr;
    float v = g_moepart[(b*2)*EMB + tid] + g_moepart[(b*2+1)*EMB + tid];
    float s = warp_sum(v), q = warp_sum(v*v);
    int w = tid >> 5, l = tid & 31;
    if (l == 0) { rs[w] = s; rq[w] = q; }
    __syncthreads();
    if (tid == 0) {
        float S = 0.f, Q = 0.f;
#pragma unroll
        for (int i = 0; i < 12; i++) { S += rs[i]; Q += rq[i]; }
        float m = S*(1.0f/EMB);
        mm = m; rr = rsqrtf(Q*(1.0f/EMB) - m*m + 1e-5f);
    }
    __syncthreads();
    hl[tid] = (v-mm)*rr*g2[tid] + b2[tid];
    __syncthreads();
#pragma unroll
    for (int rblk = 0; rblk < 3; rblk++) {
        int c = tid + 384*rblk;
        if (c < NCLS) {
            float acc = bh[c];
            const float4* Wr = (const float4*)(Wh + (size_t)c*EMB);
#pragma unroll 8
            for (int k = 0; k < 96; k++) {
                float4 wv = Wr[k];
                acc += hl[4*k]*wv.x + hl[4*k+1]*wv.y + hl[4*k+2]*wv.z + hl[4*k+3]*wv.w;
            }
            out[b*NCLS + c] = acc;
        }
    }
}

// ---------------- launcher ----------------
extern "C" void kernel_launch(void* const* d_in, const int* in_sizes, int n_in,
                              void* d_out, int out_size) {
    const float* x         = (const float*)d_in[0];
    const float* conv_w    = (const float*)d_in[1];
    const float* conv_b    = (const float*)d_in[2];
    const float* cls_token = (const float*)d_in[3];
    const float* pos_embed = (const float*)d_in[4];
    const float* ln1_g     = (const float*)d_in[5];
    const float* ln1_b     = (const float*)d_in[6];
    const float* in_proj_w = (const float*)d_in[7];
    const float* in_proj_b = (const float*)d_in[8];
    const float* out_proj_w= (const float*)d_in[9];
    const float* out_proj_b= (const float*)d_in[10];
    const float* router_w  = (const float*)d_in[11];
    const float* router_b  = (const float*)d_in[12];
    const float* ew1       = (const float*)d_in[13];
    const float* eb1       = (const float*)d_in[14];
    const float* ew2       = (const float*)d_in[15];
    const float* eb2       = (const float*)d_in[16];
    const float* ln2_g     = (const float*)d_in[17];
    const float* ln2_b     = (const float*)d_in[18];
    const float* head_w    = (const float*)d_in[19];
    const float* head_b    = (const float*)d_in[20];
    float* out = (float*)d_out;

    cudaFuncSetAttribute(k1_patch_mma, cudaFuncAttributeMaxDynamicSharedMemorySize, SMEM_GEMM);
    cudaFuncSetAttribute(k3_kv_mma,    cudaFuncAttributeMaxDynamicSharedMemorySize, SMEM_GEMM);

    k0_cls<<<BATCH, EMB>>>(cls_token, pos_embed);
    k1_patch_mma<<<dim3(MPATCH/128, EMB/128), 256, SMEM_GEMM>>>(x, conv_w, conv_b, pos_embed);
    k2_ln<<<MTOK, 128>>>(ln1_g, ln1_b);
    k3_kv_mma<<<dim3(MTOK/128, 768/128), 256, SMEM_GEMM>>>(in_proj_w, in_proj_b);
    k4_q<<<BATCH, EMB>>>(in_proj_w, in_proj_b);
    k5_attn<<<BATCH*HEADS, 256>>>();
    k6_proj_ln<<<BATCH, EMB>>>(out_proj_w, out_proj_b, ln1_g, ln1_b);
    k7_router<<<BATCH, 128>>>(router_w, router_b);
    k7b_build<<<1, 256>>>();
    k8_moe<<<dim3(NE, 256/MOE_TOK), 384>>>(ew1, eb1, ew2, eb2);
    k9_head<<<BATCH, EMB>>>(ln2_g, ln2_b, head_w, head_b, out);
}